// round 12
// baseline (speedup 1.0000x reference)
#include <cuda_runtime.h>
#include <cuda_fp16.h>
#include <cstdint>

// ---------------------------------------------------------------------------
// Model constants
// ---------------------------------------------------------------------------
#define BATCH     8
#define SEQ       512
#define INPUT_DIM 32
#define DMODEL    256
#define NLAYERS   4
#define DSTATE    16
#define DCONV     4
#define DINNER    512
#define DTRANK    16
#define MROWS     (BATCH*SEQ)    // 4096
#define LN_EPS    1e-5f

// ---------------------------------------------------------------------------
// Device scratch
// ---------------------------------------------------------------------------
__device__ float  g_h   [MROWS * DMODEL];
__device__ __half g_xnh [MROWS * DMODEL];
__device__ float  g_xz  [MROWS * 2 * DINNER];
__device__ __half g_uh  [MROWS * DINNER];
__device__ __half g_yh  [MROWS * DINNER];
__device__ float  g_t1  [BATCH * DMODEL];
__device__ float  g_part[2 * MROWS * DMODEL];     // split-K partials

// half scratch for converted inputs/weights (offsets in halves)
#define X_H    0          // x:            131072
#define IPW_H  131072     // input_proj_w: 8192
#define INW_H  139264     // in_proj_w:    1048576 (l*262144)
#define XPW_H  1187840    // x_proj_w:     98304   (l*24576)
#define OPW_H  1286144    // out_proj_w:   524288  (l*131072)
#define WH_TOTAL 1810432
__device__ __half g_wh[WH_TOTAL];

// ---------------------------------------------------------------------------
// PTX helpers
// ---------------------------------------------------------------------------
__device__ __forceinline__ void mma_f16(float* cc, const uint32_t* a, const uint32_t* b) {
    asm volatile("mma.sync.aligned.m16n8k16.row.col.f32.f16.f16.f32 "
                 "{%0,%1,%2,%3}, {%4,%5,%6,%7}, {%8,%9}, {%0,%1,%2,%3};"
                 : "+f"(cc[0]), "+f"(cc[1]), "+f"(cc[2]), "+f"(cc[3])
                 : "r"(a[0]), "r"(a[1]), "r"(a[2]), "r"(a[3]),
                   "r"(b[0]), "r"(b[1]));
}

__device__ __forceinline__ uint32_t smem_u32(const void* p) {
    uint32_t a;
    asm("{ .reg .u64 t; cvta.to.shared.u64 t, %1; cvt.u32.u64 %0, t; }"
        : "=r"(a) : "l"(p));
    return a;
}

__device__ __forceinline__ void cpasync16(uint32_t dst, const void* src, int src_sz) {
    asm volatile("cp.async.cg.shared.global [%0], [%1], 16, %2;"
                 :: "r"(dst), "l"(src), "r"(src_sz) : "memory");
}
#define CP_COMMIT()  asm volatile("cp.async.commit_group;" ::: "memory")
#define CP_WAIT(n)   asm volatile("cp.async.wait_group %0;" :: "n"(n) : "memory")

// ---------------------------------------------------------------------------
// fp16 mma.sync NT GEMM, BK=16, 4-stage cp.async pipeline (48KB static SMEM).
//   C[m,n] = sum_k A[m,k] * W[n,k]   (+bias)   fp32 accumulate/output
// CTA 128x128, 256 threads (8 warps, warp tile 32x64).
// ---------------------------------------------------------------------------
#define BM 128
#define BN 128
#define SLDH 24
#define STAGE_H (BM * SLDH)    // 3072 halves = 6KB

__global__ __launch_bounds__(256)
void gemm_h(const __half* __restrict__ A, int lda,
            const __half* __restrict__ W, int ldw,
            const float* __restrict__ bias,
            float* __restrict__ C, int ldc, size_t zstride,
            int N, int Klen)
{
    __shared__ __half Asm[4][STAGE_H];   // 24 KB
    __shared__ __half Bsm[4][STAGE_H];   // 24 KB

    const int tid  = threadIdx.x;
    const int wid  = tid >> 5;
    const int lane = tid & 31;
    const int wm   = wid & 3;
    const int wn   = wid >> 2;
    const int g    = lane >> 2;
    const int c    = lane & 3;
    const int m0   = wm * 32;
    const int n0   = wn * 64;

    const int row0 = blockIdx.y * BM;
    const int col0 = blockIdx.x * BN;
    const int kofs = blockIdx.z * Klen;
    C += (size_t)blockIdx.z * zstride;

    const int cr = tid >> 1;
    const int ck = (tid & 1) * 8;
    const int bvalid = (col0 + cr) < N ? 16 : 0;

    const uint32_t smA = smem_u32(Asm);
    const uint32_t smB = smem_u32(Bsm);
    const int T = Klen / 16;

    auto issue = [&](int t) {
        if (t < T) {
            const __half* Ap = A + (size_t)(row0 + cr) * lda + kofs + t * 16 + ck;
            cpasync16(smA + ((t & 3) * STAGE_H + cr * SLDH + ck) * 2, Ap, 16);
            const __half* Wp = W + (size_t)(col0 + cr) * ldw + kofs + t * 16 + ck;
            cpasync16(smB + ((t & 3) * STAGE_H + cr * SLDH + ck) * 2, Wp, bvalid);
        }
    };

    issue(0); CP_COMMIT();
    issue(1); CP_COMMIT();
    issue(2); CP_COMMIT();

    float acc[2][8][4];
#pragma unroll
    for (int mi = 0; mi < 2; mi++)
#pragma unroll
        for (int ni = 0; ni < 8; ni++)
#pragma unroll
            for (int e = 0; e < 4; e++) acc[mi][ni][e] = 0.f;

    for (int t = 0; t < T; t++) {
        CP_WAIT(2);
        __syncthreads();          // readers of stage (t-1)&3 are done
        issue(t + 3);
        CP_COMMIT();

        const __half* As = Asm[t & 3];
        const __half* Bs = Bsm[t & 3];

        uint32_t a[2][4], b[8][2];
#pragma unroll
        for (int mi = 0; mi < 2; mi++) {
            const int r = m0 + mi * 16 + g;
            a[mi][0] = *(const uint32_t*)&As[(r    ) * SLDH + 2 * c];
            a[mi][1] = *(const uint32_t*)&As[(r + 8) * SLDH + 2 * c];
            a[mi][2] = *(const uint32_t*)&As[(r    ) * SLDH + 2 * c + 8];
            a[mi][3] = *(const uint32_t*)&As[(r + 8) * SLDH + 2 * c + 8];
        }
#pragma unroll
        for (int ni = 0; ni < 8; ni++) {
            const int r = n0 + ni * 8 + g;
            b[ni][0] = *(const uint32_t*)&Bs[r * SLDH + 2 * c];
            b[ni][1] = *(const uint32_t*)&Bs[r * SLDH + 2 * c + 8];
        }
#pragma unroll
        for (int mi = 0; mi < 2; mi++)
#pragma unroll
            for (int ni = 0; ni < 8; ni++)
                mma_f16(acc[mi][ni], a[mi], b[ni]);
    }

    // ---- epilogue ----
#pragma unroll
    for (int mi = 0; mi < 2; mi++) {
#pragma unroll
        for (int ni = 0; ni < 8; ni++) {
            const int colb = col0 + n0 + ni * 8;
            if (colb < N) {
                const int cc = colb + c * 2;
#pragma unroll
                for (int half = 0; half < 2; half++) {
                    const int r = row0 + m0 + mi * 16 + g + half * 8;
                    float2 v = make_float2(acc[mi][ni][half * 2],
                                           acc[mi][ni][half * 2 + 1]);
                    if (bias) { v.x += bias[cc]; v.y += bias[cc + 1]; }
                    *(float2*)(C + (size_t)r * ldc + cc) = v;
                }
            }
        }
    }
}

// ---------------------------------------------------------------------------
// Merged fp32->fp16 conversion of all inputs/weights into g_wh
// ---------------------------------------------------------------------------
__global__ __launch_bounds__(256)
void cvt_all(const float* __restrict__ x,   const float* __restrict__ ipw,
             const float* __restrict__ inw, const float* __restrict__ xpw,
             const float* __restrict__ opw, __half* __restrict__ dst)
{
    int i = (blockIdx.x * blockDim.x + threadIdx.x) * 8;
    if (i >= WH_TOTAL) return;
    const float* src;
    int off;
    if      (i < IPW_H) { src = x;   off = i - X_H;   }
    else if (i < INW_H) { src = ipw; off = i - IPW_H; }
    else if (i < XPW_H) { src = inw; off = i - INW_H; }
    else if (i < OPW_H) { src = xpw; off = i - XPW_H; }
    else                { src = opw; off = i - OPW_H; }
    float4 v0 = *(const float4*)(src + off);
    float4 v1 = *(const float4*)(src + off + 4);
    __half2* d2 = (__half2*)(dst + i);
    d2[0] = __floats2half2_rn(v0.x, v0.y);
    d2[1] = __floats2half2_rn(v0.z, v0.w);
    d2[2] = __floats2half2_rn(v1.x, v1.y);
    d2[3] = __floats2half2_rn(v1.z, v1.w);
}

// ---------------------------------------------------------------------------
// Fused: h = resid + sum_z part, then LayerNorm -> fp16 xn. Block per row.
// ---------------------------------------------------------------------------
__global__ __launch_bounds__(256)
void reduce_ln_kernel(const float* __restrict__ part, size_t zstride, int nz,
                      const float* __restrict__ resid,
                      const float* __restrict__ w, const float* __restrict__ b,
                      float* __restrict__ h, __half* __restrict__ xnh)
{
    __shared__ float red_s[8], red_ss[8];
    const int r = blockIdx.x;
    const int t = threadIdx.x;
    const size_t idx = (size_t)r * DMODEL + t;

    float v = resid[idx];
    for (int z = 0; z < nz; z++) v += part[(size_t)z * zstride + idx];
    h[idx] = v;

    float s = v, ss = v * v;
#pragma unroll
    for (int off = 16; off > 0; off >>= 1) {
        s  += __shfl_xor_sync(0xffffffffu, s,  off);
        ss += __shfl_xor_sync(0xffffffffu, ss, off);
    }
    const int wid = t >> 5;
    if ((t & 31) == 0) { red_s[wid] = s; red_ss[wid] = ss; }
    __syncthreads();
    if (t < 8) { s = red_s[t]; ss = red_ss[t]; }
    else       { s = 0.f; ss = 0.f; }
    if (t < 32) {
#pragma unroll
        for (int off = 4; off > 0; off >>= 1) {
            s  += __shfl_xor_sync(0xffffffffu, s,  off);
            ss += __shfl_xor_sync(0xffffffffu, ss, off);
        }
        if (t == 0) { red_s[0] = s; red_ss[0] = ss; }
    }
    __syncthreads();
    float mean = red_s[0] * (1.f / DMODEL);
    float var  = red_ss[0] * (1.f / DMODEL) - mean * mean;
    float rstd = rsqrtf(var + LN_EPS);
    xnh[idx] = __float2half_rn((v - mean) * rstd * w[t] + b[t]);
}

// ---------------------------------------------------------------------------
// Causal depthwise conv (width 4) + SiLU; writes fp16 uh (x_proj operand only)
// ---------------------------------------------------------------------------
__global__ __launch_bounds__(256)
void conv_silu_kernel(const float* __restrict__ xz,
                      const float* __restrict__ cw, const float* __restrict__ cb,
                      __half* __restrict__ uh)
{
    int idx = blockIdx.x * blockDim.x + threadIdx.x;
    if (idx >= MROWS * DINNER) return;
    int d = idx & (DINNER - 1);
    int t = (idx >> 9) & (SEQ - 1);
    int b = idx >> 18;

    const float* base = xz + (size_t)(b * SEQ) * (2 * DINNER) + d;
    float acc = cb[d];
#pragma unroll
    for (int k = 0; k < DCONV; k++) {
        int tt = t - (DCONV - 1) + k;
        if (tt >= 0) acc += base[(size_t)tt * (2 * DINNER)] * cw[d * DCONV + k];
    }
    uh[idx] = __float2half_rn(acc / (1.f + __expf(-acc)));
}

// ---------------------------------------------------------------------------
// Selective scan v4b: cp.async staged chunks (TC=32) + in-kernel pre-pass.
// Thread (p = tid>>4 -> local d, s = tid&15 -> state).
// FIX vs R11: pre-passes now compute outputs for the thread's OWN channel p
// at timesteps tt in {s, s+16} (weights/slot channel match).
// Stage (floats): XZU 560 | Z 512 | BC 1536 | BC2 1536 | UC 512 | DTC 512
// ---------------------------------------------------------------------------
#define TC 32
#define S_XZU 0
#define S_Z   560
#define S_BC  1072
#define S_BC2 2608
#define S_UC  4144
#define S_DTC 4656
#define SSTAGE 5168          // floats; 20672 B per stage

__global__ __launch_bounds__(256)
void scan_kernel(const float* __restrict__ part,   // 2 x_proj partials
                 const float* __restrict__ xz,
                 const float* __restrict__ cw, const float* __restrict__ cb,
                 const float* __restrict__ dtw, const float* __restrict__ dtb,
                 const float* __restrict__ A_log, const float* __restrict__ Dvec,
                 __half* __restrict__ yh)
{
    __shared__ float stage[2][SSTAGE];

    const int tid = threadIdx.x;
    const int p   = tid >> 4;            // local d
    const int s   = tid & 15;            // state
    const int b   = blockIdx.x >> 5;     // batch
    const int d0  = (blockIdx.x & 31) * 16;
    const int d   = d0 + p;

    const uint32_t smBase = smem_u32(stage);
    const size_t rowbase = (size_t)b * SEQ;

    // chunks of 16B per stage: xzu 140, z 128, bc 384, bc2 384 -> 1036
    auto load_chunk = [&](int c) {
        if (c >= SEQ / TC) return;
        const int t0 = c * TC;
        const uint32_t dst0 = smBase + (c & 1) * SSTAGE * 4;
#pragma unroll
        for (int k = 0; k < 5; k++) {
            const int o = tid + k * 256;
            if (o >= 1036) break;
            const float* src;
            int soff, sz = 16;
            if (o < 140) {               // xz u-half rows t0-3 .. t0+31
                const int r = o >> 2, q = o & 3;
                const int t = t0 - 3 + r;
                const int tc = t < 0 ? 0 : t;
                src  = xz + (rowbase + tc) * (2 * DINNER) + d0 + q * 4;
                if (t < 0) sz = 0;       // zero-fill causal padding
                soff = S_XZU + r * 16 + q * 4;
            } else if (o < 268) {        // z
                const int i = o - 140, t = i >> 2, q = i & 3;
                src  = xz + (rowbase + t0 + t) * (2 * DINNER) + DINNER + d0 + q * 4;
                soff = S_Z + t * 16 + q * 4;
            } else if (o < 652) {        // bc partial 0
                const int i = o - 268, t = i / 12, q = i % 12;
                src  = part + (rowbase + t0 + t) * 48 + q * 4;
                soff = S_BC + t * 48 + q * 4;
            } else {                     // bc partial 1
                const int i = o - 652, t = i / 12, q = i % 12;
                src  = part + (size_t)MROWS * 48 + (rowbase + t0 + t) * 48 + q * 4;
                soff = S_BC2 + t * 48 + q * 4;
            }
            cpasync16(dst0 + soff * 4, src, sz);
        }
    };

    // per-thread constants (for channel d = d0 + p)
    const float A   = -__expf(A_log[d * DSTATE + s]);
    const float Dp  = Dvec[d];
    const float4 cwv = *(const float4*)(cw + d * DCONV);
    const float cbv  = cb[d];
    float w16[16];
    {
        const float4* wp = (const float4*)(dtw + d * DTRANK);
#pragma unroll
        for (int q = 0; q < 4; q++) {
            float4 w4 = wp[q];
            w16[4*q+0] = w4.x; w16[4*q+1] = w4.y;
            w16[4*q+2] = w4.z; w16[4*q+3] = w4.w;
        }
    }
    const float dtbv = dtb[d];
    float h = 0.f;

    __half* y_p = yh + rowbase * DINNER + d;

    load_chunk(0); CP_COMMIT();

    for (int c = 0; c < SEQ / TC; c++) {
        load_chunk(c + 1);
        CP_COMMIT();
        CP_WAIT(1);
        __syncthreads();

        float* st = stage[c & 1];
        const int t0 = c * TC;

        // --- pre-pass A: sum bc partials (d-independent, any mapping ok);
        //                 compute u for OWN channel p at tt = s, s+16 ---
#pragma unroll
        for (int k = 0; k < 6; k++) {
            const int i = tid + k * 256;   // 1536 bc elements
            st[S_BC + i] += st[S_BC2 + i];
        }
#pragma unroll
        for (int k = 0; k < 2; k++) {
            const int tt = s + k * 16;
            float acc = cbv
                + st[S_XZU + (tt + 0) * 16 + p] * cwv.x
                + st[S_XZU + (tt + 1) * 16 + p] * cwv.y
                + st[S_XZU + (tt + 2) * 16 + p] * cwv.z
                + st[S_XZU + (tt + 3) * 16 + p] * cwv.w;
            st[S_UC + tt * 16 + p] = acc / (1.f + __expf(-acc));
        }
        __syncthreads();   // bc sums ready for dt

        // --- pre-pass B: dt for OWN channel p at tt = s, s+16 ---
#pragma unroll
        for (int k = 0; k < 2; k++) {
            const int tt = s + k * 16;
            float dot = dtbv;
#pragma unroll
            for (int kk = 0; kk < 16; kk++)
                dot += st[S_BC + tt * 48 + kk] * w16[kk];
            st[S_DTC + tt * 16 + p] = (dot > 20.f) ? dot : log1pf(__expf(dot));
        }
        __syncthreads();

        // --- main scan loop ---
#pragma unroll 4
        for (int tt = 0; tt < TC; tt++) {
            float dtv = st[S_DTC + tt * 16 + p];
            float uv  = st[S_UC  + tt * 16 + p];
            float Bv  = st[S_BC  + tt * 48 + 16 + s];
            float Cv  = st[S_BC  + tt * 48 + 32 + s];

            h = __expf(dtv * A) * h + dtv * uv * Bv;
            float yv = h * Cv;
            yv += __shfl_xor_sync(0xffffffffu, yv, 8);
            yv += __shfl_xor_sync(0xffffffffu, yv, 4);
            yv += __shfl_xor_sync(0xffffffffu, yv, 2);
            yv += __shfl_xor_sync(0xffffffffu, yv, 1);

            if (s == 0) {
                float zv  = st[S_Z + tt * 16 + p];
                float out = (yv + uv * Dp) * (zv / (1.f + __expf(-zv)));
                y_p[(size_t)(t0 + tt) * DINNER] = __float2half_rn(out);
            }
        }
        __syncthreads();   // readers done before buffer reuse
    }
}

// ---------------------------------------------------------------------------
// Head
// ---------------------------------------------------------------------------
__global__ __launch_bounds__(256)
void head1_kernel(const float* __restrict__ h,
                  const float* __restrict__ w1, const float* __restrict__ b1,
                  float* __restrict__ t1)
{
    __shared__ float hs[DMODEL];
    int b = blockIdx.x;
    int n = threadIdx.x;
    hs[n] = h[((size_t)b * SEQ + (SEQ - 1)) * DMODEL + n];
    __syncthreads();

    const float4* wp = (const float4*)(w1 + (size_t)n * DMODEL);
    float acc = b1[n];
#pragma unroll 8
    for (int k = 0; k < DMODEL / 4; k++) {
        float4 w4 = wp[k];
        acc += hs[4*k+0]*w4.x + hs[4*k+1]*w4.y + hs[4*k+2]*w4.z + hs[4*k+3]*w4.w;
    }
    t1[b * DMODEL + n] = fmaxf(acc, 0.f);
}

__global__ __launch_bounds__(32)
void head2_kernel(const float* __restrict__ t1,
                  const float* __restrict__ w2, const float* __restrict__ b2,
                  float* __restrict__ out)
{
    int b = blockIdx.x;
    int lane = threadIdx.x;
    float acc = 0.f;
#pragma unroll
    for (int k = lane; k < DMODEL; k += 32)
        acc += t1[b * DMODEL + k] * w2[k];
#pragma unroll
    for (int off = 16; off > 0; off >>= 1)
        acc += __shfl_xor_sync(0xffffffffu, acc, off);
    if (lane == 0) out[b] = acc + b2[0];
}

// ---------------------------------------------------------------------------
// Host launcher
// ---------------------------------------------------------------------------
extern "C" void kernel_launch(void* const* d_in, const int* in_sizes, int n_in,
                              void* d_out, int out_size)
{
    const float* x            = (const float*)d_in[0];
    const float* input_proj_w = (const float*)d_in[1];
    const float* input_proj_b = (const float*)d_in[2];
    const float* ln_w         = (const float*)d_in[3];
    const float* ln_b         = (const float*)d_in[4];
    const float* in_proj_w    = (const float*)d_in[5];
    const float* conv_w       = (const float*)d_in[6];
    const float* conv_b       = (const float*)d_in[7];
    const float* x_proj_w     = (const float*)d_in[8];
    const float* dt_proj_w    = (const float*)d_in[9];
    const float* dt_proj_b    = (const float*)d_in[10];
    const float* A_log        = (const float*)d_in[11];
    const float* Dvec         = (const float*)d_in[12];
    const float* out_proj_w   = (const float*)d_in[13];
    const float* head_w1      = (const float*)d_in[14];
    const float* head_b1      = (const float*)d_in[15];
    const float* head_w2      = (const float*)d_in[16];
    const float* head_b2      = (const float*)d_in[17];
    float* out = (float*)d_out;

    float  *p_h, *p_xz, *p_t1, *p_part;
    __half *p_xnh, *p_uh, *p_yh, *p_wh;
    cudaGetSymbolAddress((void**)&p_h,    g_h);
    cudaGetSymbolAddress((void**)&p_xnh,  g_xnh);
    cudaGetSymbolAddress((void**)&p_xz,   g_xz);
    cudaGetSymbolAddress((void**)&p_uh,   g_uh);
    cudaGetSymbolAddress((void**)&p_yh,   g_yh);
    cudaGetSymbolAddress((void**)&p_t1,   g_t1);
    cudaGetSymbolAddress((void**)&p_part, g_part);
    cudaGetSymbolAddress((void**)&p_wh,   g_wh);

    // convert all fp32 operands to fp16 scratch (one launch)
    cvt_all<<<(WH_TOTAL / 8 + 255) / 256, 256>>>(
        x, input_proj_w, in_proj_w, x_proj_w, out_proj_w, p_wh);

    // input projection  (N=256, K=32)
    gemm_h<<<dim3(DMODEL/BN, MROWS/BM, 1), 256>>>(
        p_wh + X_H, INPUT_DIM, p_wh + IPW_H, INPUT_DIM, input_proj_b,
        p_h, DMODEL, 0, DMODEL, INPUT_DIM);

    // LN of initial h (nz=0)
    reduce_ln_kernel<<<MROWS, 256>>>(nullptr, 0, 0, p_h,
                                     ln_w, ln_b, p_h, p_xnh);

    for (int l = 0; l < NLAYERS; l++) {
        // in_proj  (N=1024, K=256)
        gemm_h<<<dim3((2*DINNER)/BN, MROWS/BM, 1), 256>>>(
            p_xnh, DMODEL, p_wh + INW_H + (size_t)l * 2 * DINNER * DMODEL, DMODEL,
            nullptr, p_xz, 2 * DINNER, 0, 2 * DINNER, DMODEL);

        // conv + silu -> uh (x_proj operand)
        conv_silu_kernel<<<(MROWS * DINNER) / 256, 256>>>(
            p_xz, conv_w + l * DINNER * DCONV, conv_b + l * DINNER, p_uh);

        // x_proj (N=48, K=512), split-K=2 -> 2 partials in g_part
        gemm_h<<<dim3(1, MROWS/BM, 2), 256>>>(
            p_uh, DINNER, p_wh + XPW_H + (size_t)l * 48 * DINNER, DINNER,
            nullptr, p_part, 48, (size_t)MROWS * 48, 48, DINNER / 2);

        // selective scan (sums partials, computes u/dt in pre-pass)
        scan_kernel<<<256, 256>>>(
            p_part, p_xz,
            conv_w + l * DINNER * DCONV, conv_b + l * DINNER,
            dt_proj_w + (size_t)l * DINNER * DTRANK, dt_proj_b + l * DINNER,
            A_log + (size_t)l * DINNER * DSTATE, Dvec + l * DINNER, p_yh);

        // out_proj (N=256, K=512) split-K=2
        gemm_h<<<dim3(DMODEL/BN, MROWS/BM, 2), 256>>>(
            p_yh, DINNER, p_wh + OPW_H + (size_t)l * DMODEL * DINNER, DINNER,
            nullptr, p_part, DMODEL, (size_t)MROWS * DMODEL, DMODEL, DINNER / 2);

        // fused residual reduce + LN (next layer's xn; harmless on last layer)
        reduce_ln_kernel<<<MROWS, 256>>>(
            p_part, (size_t)MROWS * DMODEL, 2, p_h,
            ln_w + ((l + 1 < NLAYERS) ? (l + 1) : l) * DMODEL,
            ln_b + ((l + 1 < NLAYERS) ? (l + 1) : l) * DMODEL,
            p_h, p_xnh);
    }

    // head
    head1_kernel<<<BATCH, DMODEL>>>(p_h, head_w1, head_b1, p_t1);
    head2_kernel<<<BATCH, 32>>>(p_t1, head_w2, head_b2, out);
}

// round 13
// speedup vs baseline: 1.1108x; 1.1108x over previous
#include <cuda_runtime.h>
#include <cuda_fp16.h>
#include <cstdint>

// ---------------------------------------------------------------------------
// Model constants
// ---------------------------------------------------------------------------
#define BATCH     8
#define SEQ       512
#define INPUT_DIM 32
#define DMODEL    256
#define NLAYERS   4
#define DSTATE    16
#define DCONV     4
#define DINNER    512
#define DTRANK    16
#define MROWS     (BATCH*SEQ)    // 4096
#define LN_EPS    1e-5f

// ---------------------------------------------------------------------------
// Device scratch
// ---------------------------------------------------------------------------
__device__ float  g_h   [MROWS * DMODEL];
__device__ __half g_xnh [MROWS * DMODEL];
__device__ float  g_xz  [MROWS * 2 * DINNER];
__device__ float  g_u   [MROWS * DINNER];
__device__ __half g_uh  [MROWS * DINNER];
__device__ float  g_dbl [MROWS * 48];
__device__ float  g_dt  [MROWS * DINNER];
__device__ __half g_yh  [MROWS * DINNER];
__device__ float  g_part[4 * MROWS * 48 > 2 * MROWS * DMODEL ?
                         4 * MROWS * 48 : 2 * MROWS * DMODEL];

// half scratch for converted inputs/weights (offsets in halves)
#define X_H    0          // x:            131072
#define IPW_H  131072     // input_proj_w: 8192
#define INW_H  139264     // in_proj_w:    1048576 (l*262144)
#define XPW_H  1187840    // x_proj_w:     98304   (l*24576)
#define OPW_H  1286144    // out_proj_w:   524288  (l*131072)
#define WH_TOTAL 1810432
__device__ __half g_wh[WH_TOTAL];

// ---------------------------------------------------------------------------
// PTX helpers
// ---------------------------------------------------------------------------
__device__ __forceinline__ void mma_f16(float* cc, const uint32_t* a, const uint32_t* b) {
    asm volatile("mma.sync.aligned.m16n8k16.row.col.f32.f16.f16.f32 "
                 "{%0,%1,%2,%3}, {%4,%5,%6,%7}, {%8,%9}, {%0,%1,%2,%3};"
                 : "+f"(cc[0]), "+f"(cc[1]), "+f"(cc[2]), "+f"(cc[3])
                 : "r"(a[0]), "r"(a[1]), "r"(a[2]), "r"(a[3]),
                   "r"(b[0]), "r"(b[1]));
}

__device__ __forceinline__ uint32_t smem_u32(const void* p) {
    uint32_t a;
    asm("{ .reg .u64 t; cvta.to.shared.u64 t, %1; cvt.u32.u64 %0, t; }"
        : "=r"(a) : "l"(p));
    return a;
}

__device__ __forceinline__ void cpasync16(uint32_t dst, const void* src, int src_sz) {
    asm volatile("cp.async.cg.shared.global [%0], [%1], 16, %2;"
                 :: "r"(dst), "l"(src), "r"(src_sz) : "memory");
}
#define CP_COMMIT()  asm volatile("cp.async.commit_group;" ::: "memory")
#define CP_WAIT(n)   asm volatile("cp.async.wait_group %0;" :: "n"(n) : "memory")

// ---------------------------------------------------------------------------
// fp16 mma.sync NT GEMM, BK=32, cp.async double buffer (40KB static SMEM).
// (R10-proven configuration)
// ---------------------------------------------------------------------------
#define BM 128
#define BN 128
#define BKH 32
#define SLDH 40
#define STAGE_H (BM * SLDH)    // 5120 halves

__global__ __launch_bounds__(256)
void gemm_h(const __half* __restrict__ A, int lda,
            const __half* __restrict__ W, int ldw,
            const float* __restrict__ bias,
            float* __restrict__ C, int ldc, size_t zstride,
            int N, int Klen)
{
    __shared__ __half Asm[2][STAGE_H];
    __shared__ __half Bsm[2][STAGE_H];

    const int tid  = threadIdx.x;
    const int wid  = tid >> 5;
    const int lane = tid & 31;
    const int wm   = wid & 3;
    const int wn   = wid >> 2;
    const int g    = lane >> 2;
    const int c    = lane & 3;
    const int m0   = wm * 32;
    const int n0   = wn * 64;

    const int row0 = blockIdx.y * BM;
    const int col0 = blockIdx.x * BN;
    const int kofs = blockIdx.z * Klen;
    C += (size_t)blockIdx.z * zstride;

    const int cr = tid >> 1;
    const int ck = (tid & 1) * 16;
    const int bvalid = (col0 + cr) < N ? 16 : 0;

    const uint32_t smA = smem_u32(Asm);
    const uint32_t smB = smem_u32(Bsm);
    const int T = Klen / BKH;

    auto issue = [&](int t) {
        if (t < T) {
            const __half* Ap = A + (size_t)(row0 + cr) * lda + kofs + t * BKH + ck;
            uint32_t da = smA + ((t & 1) * STAGE_H + cr * SLDH + ck) * 2;
            cpasync16(da,      Ap,     16);
            cpasync16(da + 16, Ap + 8, 16);
            const __half* Wp = W + (size_t)(col0 + cr) * ldw + kofs + t * BKH + ck;
            uint32_t db = smB + ((t & 1) * STAGE_H + cr * SLDH + ck) * 2;
            cpasync16(db,      Wp,     bvalid);
            cpasync16(db + 16, Wp + 8, bvalid);
        }
    };

    issue(0); CP_COMMIT();

    float acc[2][8][4];
#pragma unroll
    for (int mi = 0; mi < 2; mi++)
#pragma unroll
        for (int ni = 0; ni < 8; ni++)
#pragma unroll
            for (int e = 0; e < 4; e++) acc[mi][ni][e] = 0.f;

    for (int t = 0; t < T; t++) {
        issue(t + 1);
        CP_COMMIT();
        CP_WAIT(1);
        __syncthreads();

        const __half* As = Asm[t & 1];
        const __half* Bs = Bsm[t & 1];

#pragma unroll
        for (int ks = 0; ks < 2; ks++) {
            const int kb = ks * 16;
            uint32_t a[2][4], b[8][2];
#pragma unroll
            for (int mi = 0; mi < 2; mi++) {
                const int r = m0 + mi * 16 + g;
                a[mi][0] = *(const uint32_t*)&As[(r    ) * SLDH + kb + 2 * c];
                a[mi][1] = *(const uint32_t*)&As[(r + 8) * SLDH + kb + 2 * c];
                a[mi][2] = *(const uint32_t*)&As[(r    ) * SLDH + kb + 2 * c + 8];
                a[mi][3] = *(const uint32_t*)&As[(r + 8) * SLDH + kb + 2 * c + 8];
            }
#pragma unroll
            for (int ni = 0; ni < 8; ni++) {
                const int r = n0 + ni * 8 + g;
                b[ni][0] = *(const uint32_t*)&Bs[r * SLDH + kb + 2 * c];
                b[ni][1] = *(const uint32_t*)&Bs[r * SLDH + kb + 2 * c + 8];
            }
#pragma unroll
            for (int mi = 0; mi < 2; mi++)
#pragma unroll
                for (int ni = 0; ni < 8; ni++)
                    mma_f16(acc[mi][ni], a[mi], b[ni]);
        }
        __syncthreads();
    }

    // ---- epilogue ----
#pragma unroll
    for (int mi = 0; mi < 2; mi++) {
#pragma unroll
        for (int ni = 0; ni < 8; ni++) {
            const int colb = col0 + n0 + ni * 8;
            if (colb < N) {
                const int cc = colb + c * 2;
#pragma unroll
                for (int half = 0; half < 2; half++) {
                    const int r = row0 + m0 + mi * 16 + g + half * 8;
                    float2 v = make_float2(acc[mi][ni][half * 2],
                                           acc[mi][ni][half * 2 + 1]);
                    if (bias) { v.x += bias[cc]; v.y += bias[cc + 1]; }
                    *(float2*)(C + (size_t)r * ldc + cc) = v;
                }
            }
        }
    }
}

// ---------------------------------------------------------------------------
// Merged fp32->fp16 conversion of all inputs/weights into g_wh
// ---------------------------------------------------------------------------
__global__ __launch_bounds__(256)
void cvt_all(const float* __restrict__ x,   const float* __restrict__ ipw,
             const float* __restrict__ inw, const float* __restrict__ xpw,
             const float* __restrict__ opw, __half* __restrict__ dst)
{
    int i = (blockIdx.x * blockDim.x + threadIdx.x) * 8;
    if (i >= WH_TOTAL) return;
    const float* src;
    int off;
    if      (i < IPW_H) { src = x;   off = i - X_H;   }
    else if (i < INW_H) { src = ipw; off = i - IPW_H; }
    else if (i < XPW_H) { src = inw; off = i - INW_H; }
    else if (i < OPW_H) { src = xpw; off = i - XPW_H; }
    else                { src = opw; off = i - OPW_H; }
    float4 v0 = *(const float4*)(src + off);
    float4 v1 = *(const float4*)(src + off + 4);
    __half2* d2 = (__half2*)(dst + i);
    d2[0] = __floats2half2_rn(v0.x, v0.y);
    d2[1] = __floats2half2_rn(v0.z, v0.w);
    d2[2] = __floats2half2_rn(v1.x, v1.y);
    d2[3] = __floats2half2_rn(v1.z, v1.w);
}

// ---------------------------------------------------------------------------
// Fused residual reduce + LayerNorm, warp-per-row (8 rows/block, 512 blocks).
//   h = resid + sum_z part;  xn = LN(h)  (fp16; skipped when xnh == null)
// ---------------------------------------------------------------------------
__global__ __launch_bounds__(256)
void reduce_ln_kernel(const float* __restrict__ part, size_t zstride, int nz,
                      const float* __restrict__ resid,
                      const float* __restrict__ w, const float* __restrict__ b,
                      float* __restrict__ h, __half* __restrict__ xnh)
{
    const int row  = blockIdx.x * 8 + (threadIdx.x >> 5);
    const int lane = threadIdx.x & 31;
    const size_t base = (size_t)row * DMODEL;

    float v[8];
    float s = 0.f, ss = 0.f;
#pragma unroll
    for (int i = 0; i < 8; i++) {
        const int c = lane + i * 32;
        float t = resid[base + c];
        for (int z = 0; z < nz; z++) t += part[(size_t)z * zstride + base + c];
        v[i] = t;
        s  += t;
        ss += t * t;
    }
#pragma unroll
    for (int off = 16; off > 0; off >>= 1) {
        s  += __shfl_xor_sync(0xffffffffu, s,  off);
        ss += __shfl_xor_sync(0xffffffffu, ss, off);
    }
    const float mean = s * (1.f / DMODEL);
    const float var  = ss * (1.f / DMODEL) - mean * mean;
    const float rstd = rsqrtf(var + LN_EPS);

#pragma unroll
    for (int i = 0; i < 8; i++) {
        const int c = lane + i * 32;
        if (nz) h[base + c] = v[i];
        if (xnh) xnh[base + c] = __float2half_rn((v[i] - mean) * rstd * w[c] + b[c]);
    }
}

// ---------------------------------------------------------------------------
// Fused: dbl row = sum of 4 split-K partials; dt = softplus(dbl[:16]@dtw^T+b)
// ---------------------------------------------------------------------------
__global__ __launch_bounds__(128)
void reduce_dt_kernel(const float* __restrict__ part, size_t zstride,
                      const float* __restrict__ dtw, const float* __restrict__ dtb,
                      float* __restrict__ dbl, float* __restrict__ dt)
{
    __shared__ float bc[48];
    const int r = blockIdx.x;
    const int t = threadIdx.x;

    if (t < 48) {
        const size_t idx = (size_t)r * 48 + t;
        float v = part[idx] + part[zstride + idx]
                + part[2 * zstride + idx] + part[3 * zstride + idx];
        bc[t] = v;
        dbl[idx] = v;
    }
    __syncthreads();

#pragma unroll
    for (int dd = 0; dd < 4; dd++) {
        const int d = t + dd * 128;
        const float4* wp = (const float4*)(dtw + d * DTRANK);
        float acc = dtb[d];
#pragma unroll
        for (int q = 0; q < 4; q++) {
            float4 w4 = wp[q];
            acc += bc[4*q+0]*w4.x + bc[4*q+1]*w4.y + bc[4*q+2]*w4.z + bc[4*q+3]*w4.w;
        }
        dt[(size_t)r * DINNER + d] = (acc > 20.f) ? acc : log1pf(__expf(acc));
    }
}

// ---------------------------------------------------------------------------
// Causal depthwise conv (width 4) + SiLU; writes fp32 (scan) + fp16 (x_proj)
// ---------------------------------------------------------------------------
__global__ __launch_bounds__(256)
void conv_silu_kernel(const float* __restrict__ xz,
                      const float* __restrict__ cw, const float* __restrict__ cb,
                      float* __restrict__ u, __half* __restrict__ uh)
{
    int idx = blockIdx.x * blockDim.x + threadIdx.x;
    if (idx >= MROWS * DINNER) return;
    int d = idx & (DINNER - 1);
    int t = (idx >> 9) & (SEQ - 1);
    int b = idx >> 18;

    const float* base = xz + (size_t)(b * SEQ) * (2 * DINNER) + d;
    float acc = cb[d];
#pragma unroll
    for (int k = 0; k < DCONV; k++) {
        int tt = t - (DCONV - 1) + k;
        if (tt >= 0) acc += base[(size_t)tt * (2 * DINNER)] * cw[d * DCONV + k];
    }
    float uv = acc / (1.f + __expf(-acc));
    u[idx]  = uv;
    uh[idx] = __float2half_rn(uv);
}

// ---------------------------------------------------------------------------
// Selective scan v3 (R10-proven): cp.async staged chunks (TC=32), dbl buffer.
// Block = 16 consecutive d of one batch (256 blocks), thread = (p, s).
// Stage layout (floats): [0:512) dt, [512:1024) u, [1024:1536) z, [1536:3072) bc
// ---------------------------------------------------------------------------
#define TC 32
#define SSTAGE 3072

__global__ __launch_bounds__(256)
void scan_kernel(const float* __restrict__ dt, const float* __restrict__ u,
                 const float* __restrict__ dbl, const float* __restrict__ xz,
                 const float* __restrict__ A_log, const float* __restrict__ Dvec,
                 __half* __restrict__ yh)
{
    __shared__ float stage[2][SSTAGE];

    const int tid = threadIdx.x;
    const int p   = tid >> 4;
    const int s   = tid & 15;
    const int b   = blockIdx.x >> 5;
    const int d0  = (blockIdx.x & 31) * 16;
    const int d   = d0 + p;

    const uint32_t smBase = smem_u32(stage);
    const size_t rowbase = (size_t)b * SEQ;

    auto load_chunk = [&](int c) {
        if (c >= SEQ / TC) return;
        const int t0 = c * TC;
        const uint32_t dst0 = smBase + (c & 1) * SSTAGE * 4;
#pragma unroll
        for (int k = 0; k < 3; k++) {
            const int o = tid + k * 256;
            const float* src;
            int soff;
            if (o < 128) {
                const int t = o >> 2, q = o & 3;
                src  = dt + (rowbase + t0 + t) * DINNER + d0 + q * 4;
                soff = t * 16 + q * 4;
            } else if (o < 256) {
                const int o2 = o - 128;
                const int t = o2 >> 2, q = o2 & 3;
                src  = u + (rowbase + t0 + t) * DINNER + d0 + q * 4;
                soff = 512 + t * 16 + q * 4;
            } else if (o < 384) {
                const int o2 = o - 256;
                const int t = o2 >> 2, q = o2 & 3;
                src  = xz + (rowbase + t0 + t) * (2 * DINNER) + DINNER + d0 + q * 4;
                soff = 1024 + t * 16 + q * 4;
            } else {
                const int o2 = o - 384;
                const int t = o2 / 12, q = o2 % 12;
                src  = dbl + (rowbase + t0 + t) * 48 + q * 4;
                soff = 1536 + t * 48 + q * 4;
            }
            cpasync16(dst0 + soff * 4, src, 16);
        }
    };

    const float A  = -__expf(A_log[d * DSTATE + s]);
    const float Dp = Dvec[d];
    float h = 0.f;

    __half* y_p = yh + rowbase * DINNER + d;

    load_chunk(0); CP_COMMIT();

    for (int c = 0; c < SEQ / TC; c++) {
        load_chunk(c + 1);
        CP_COMMIT();
        CP_WAIT(1);
        __syncthreads();

        const float* st = stage[c & 1];
        const int t0 = c * TC;

#pragma unroll 4
        for (int tt = 0; tt < TC; tt++) {
            float dtv = st[tt * 16 + p];
            float uv  = st[512 + tt * 16 + p];
            float Bv  = st[1536 + tt * 48 + 16 + s];
            float Cv  = st[1536 + tt * 48 + 32 + s];

            h = __expf(dtv * A) * h + dtv * uv * Bv;
            float yv = h * Cv;
            yv += __shfl_xor_sync(0xffffffffu, yv, 8);
            yv += __shfl_xor_sync(0xffffffffu, yv, 4);
            yv += __shfl_xor_sync(0xffffffffu, yv, 2);
            yv += __shfl_xor_sync(0xffffffffu, yv, 1);

            if (s == 0) {
                float zv  = st[1024 + tt * 16 + p];
                float out = (yv + uv * Dp) * (zv / (1.f + __expf(-zv)));
                y_p[(size_t)(t0 + tt) * DINNER] = __float2half_rn(out);
            }
        }
        __syncthreads();
    }
}

// ---------------------------------------------------------------------------
// Fused head: t1 = relu(h_last @ w1^T + b1); out[b] = t1 . w2 + b2
// One block per batch (8 blocks, 256 threads).
// ---------------------------------------------------------------------------
__global__ __launch_bounds__(256)
void head_kernel(const float* __restrict__ h,
                 const float* __restrict__ w1, const float* __restrict__ b1,
                 const float* __restrict__ w2, const float* __restrict__ b2,
                 float* __restrict__ out)
{
    __shared__ float hs[DMODEL];
    __shared__ float red[8];
    const int b = blockIdx.x;
    const int n = threadIdx.x;

    hs[n] = h[((size_t)b * SEQ + (SEQ - 1)) * DMODEL + n];
    __syncthreads();

    const float4* wp = (const float4*)(w1 + (size_t)n * DMODEL);
    float acc = b1[n];
#pragma unroll 8
    for (int k = 0; k < DMODEL / 4; k++) {
        float4 w4 = wp[k];
        acc += hs[4*k+0]*w4.x + hs[4*k+1]*w4.y + hs[4*k+2]*w4.z + hs[4*k+3]*w4.w;
    }
    float t1 = fmaxf(acc, 0.f);

    // out = sum_n t1[n] * w2[n]
    float v = t1 * w2[n];
#pragma unroll
    for (int off = 16; off > 0; off >>= 1)
        v += __shfl_xor_sync(0xffffffffu, v, off);
    if ((n & 31) == 0) red[n >> 5] = v;
    __syncthreads();
    if (n < 32) {
        float r = (n < 8) ? red[n] : 0.f;
#pragma unroll
        for (int off = 4; off > 0; off >>= 1)
            r += __shfl_xor_sync(0xffffffffu, r, off);
        if (n == 0) out[b] = r + b2[0];
    }
}

// ---------------------------------------------------------------------------
// Host launcher
// ---------------------------------------------------------------------------
extern "C" void kernel_launch(void* const* d_in, const int* in_sizes, int n_in,
                              void* d_out, int out_size)
{
    const float* x            = (const float*)d_in[0];
    const float* input_proj_w = (const float*)d_in[1];
    const float* input_proj_b = (const float*)d_in[2];
    const float* ln_w         = (const float*)d_in[3];
    const float* ln_b         = (const float*)d_in[4];
    const float* in_proj_w    = (const float*)d_in[5];
    const float* conv_w       = (const float*)d_in[6];
    const float* conv_b       = (const float*)d_in[7];
    const float* x_proj_w     = (const float*)d_in[8];
    const float* dt_proj_w    = (const float*)d_in[9];
    const float* dt_proj_b    = (const float*)d_in[10];
    const float* A_log        = (const float*)d_in[11];
    const float* Dvec         = (const float*)d_in[12];
    const float* out_proj_w   = (const float*)d_in[13];
    const float* head_w1      = (const float*)d_in[14];
    const float* head_b1      = (const float*)d_in[15];
    const float* head_w2      = (const float*)d_in[16];
    const float* head_b2      = (const float*)d_in[17];
    float* out = (float*)d_out;

    float  *p_h, *p_xz, *p_u, *p_dbl, *p_dt, *p_part;
    __half *p_xnh, *p_uh, *p_yh, *p_wh;
    cudaGetSymbolAddress((void**)&p_h,    g_h);
    cudaGetSymbolAddress((void**)&p_xnh,  g_xnh);
    cudaGetSymbolAddress((void**)&p_xz,   g_xz);
    cudaGetSymbolAddress((void**)&p_u,    g_u);
    cudaGetSymbolAddress((void**)&p_uh,   g_uh);
    cudaGetSymbolAddress((void**)&p_dbl,  g_dbl);
    cudaGetSymbolAddress((void**)&p_dt,   g_dt);
    cudaGetSymbolAddress((void**)&p_yh,   g_yh);
    cudaGetSymbolAddress((void**)&p_part, g_part);
    cudaGetSymbolAddress((void**)&p_wh,   g_wh);

    // convert all fp32 operands to fp16 scratch
    cvt_all<<<(WH_TOTAL / 8 + 255) / 256, 256>>>(
        x, input_proj_w, in_proj_w, x_proj_w, out_proj_w, p_wh);

    // input projection  (N=256, K=32)
    gemm_h<<<dim3(DMODEL/BN, MROWS/BM, 1), 256>>>(
        p_wh + X_H, INPUT_DIM, p_wh + IPW_H, INPUT_DIM, input_proj_b,
        p_h, DMODEL, 0, DMODEL, INPUT_DIM);

    // LN of initial h (nz=0: resid is h itself; h not rewritten)
    reduce_ln_kernel<<<MROWS / 8, 256>>>(nullptr, 0, 0, p_h,
                                         ln_w, ln_b, p_h, p_xnh);

    for (int l = 0; l < NLAYERS; l++) {
        // in_proj  (N=1024, K=256)
        gemm_h<<<dim3((2*DINNER)/BN, MROWS/BM, 1), 256>>>(
            p_xnh, DMODEL, p_wh + INW_H + (size_t)l * 2 * DINNER * DMODEL, DMODEL,
            nullptr, p_xz, 2 * DINNER, 0, 2 * DINNER, DMODEL);

        // conv + silu -> u (fp32) + uh (fp16)
        conv_silu_kernel<<<(MROWS * DINNER) / 256, 256>>>(
            p_xz, conv_w + l * DINNER * DCONV, conv_b + l * DINNER, p_u, p_uh);

        // x_proj (N=48, K=512), split-K=4 -> 128 CTAs
        gemm_h<<<dim3(1, MROWS/BM, 4), 256>>>(
            p_uh, DINNER, p_wh + XPW_H + (size_t)l * 48 * DINNER, DINNER,
            nullptr, p_part, 48, (size_t)MROWS * 48, 48, DINNER / 4);

        // fused split-K reduce + dt projection + softplus
        reduce_dt_kernel<<<MROWS, 128>>>(
            p_part, (size_t)MROWS * 48,
            dt_proj_w + (size_t)l * DINNER * DTRANK, dt_proj_b + l * DINNER,
            p_dbl, p_dt);

        // selective scan (SMEM-staged)
        scan_kernel<<<256, 256>>>(
            p_dt, p_u, p_dbl, p_xz,
            A_log + (size_t)l * DINNER * DSTATE, Dvec + l * DINNER, p_yh);

        // out_proj (N=256, K=512) split-K=2
        gemm_h<<<dim3(DMODEL/BN, MROWS/BM, 2), 256>>>(
            p_yh, DINNER, p_wh + OPW_H + (size_t)l * DMODEL * DINNER, DINNER,
            nullptr, p_part, DMODEL, (size_t)MROWS * DMODEL, DMODEL, DINNER / 2);

        // fused residual reduce + LN (skip xn on last layer)
        const bool last = (l + 1 == NLAYERS);
        reduce_ln_kernel<<<MROWS / 8, 256>>>(
            p_part, (size_t)MROWS * DMODEL, 2, p_h,
            ln_w + (last ? l : l + 1) * DMODEL,
            ln_b + (last ? l : l + 1) * DMODEL,
            p_h, last ? nullptr : p_xnh);
    }

    // fused head
    head_kernel<<<BATCH, 256>>>(p_h, head_w1, head_b1, head_w2, head_b2, out);
}